// round 1
// baseline (speedup 1.0000x reference)
#include <cuda_runtime.h>
#include <cuda_bf16.h>

// CG solve: X such that M X = RHS, 20 iterations, freeze once rTr <= 1e-10.
// n = 8192 (f32). Dominant cost: 20 streaming reads of the 256 MB matrix.

#define N_MAX 8192
#define CG_NITER 20
#define CG_TOL 1e-10f

// ---- persistent device state (allocation-free scratch) ----
__device__ float g_X[N_MAX];
__device__ float g_r[N_MAX];
__device__ float g_p[N_MAX];
__device__ float g_Ap[N_MAX];
__device__ float g_rTr[CG_NITER + 1];   // g_rTr[it] = ||r||^2 entering iteration it
__device__ float g_pAp[CG_NITER];

// ---- reductions ----
__device__ __forceinline__ float warp_reduce(float v) {
    #pragma unroll
    for (int o = 16; o > 0; o >>= 1) v += __shfl_xor_sync(0xffffffffu, v, o);
    return v;
}

// block reduce (blockDim.x <= 1024, multiple of 32), result valid on thread 0
__device__ __forceinline__ float block_reduce(float v) {
    __shared__ float sbuf[32];
    int lane = threadIdx.x & 31;
    int wid  = threadIdx.x >> 5;
    v = warp_reduce(v);
    if (lane == 0) sbuf[wid] = v;
    __syncthreads();
    int nw = (blockDim.x + 31) >> 5;
    v = (threadIdx.x < nw) ? sbuf[threadIdx.x] : 0.0f;
    if (wid == 0) v = warp_reduce(v);
    return v;
}

// ---- kernels ----

// zero all per-iteration scalar accumulators (single small block)
__global__ void k_init_scalars() {
    int i = threadIdx.x;
    if (i < CG_NITER + 1) g_rTr[i] = 0.0f;
    if (i < CG_NITER)     g_pAp[i] = 0.0f;
}

// X0 = 0, r0 = p0 = RHS, rTr[0] = sum(RHS^2)
__global__ void k_init_vecs(const float* __restrict__ RHS, int n) {
    int i = blockIdx.x * blockDim.x + threadIdx.x;
    float v = 0.0f;
    if (i < n) {
        float rhs = RHS[i];
        g_X[i] = 0.0f;
        g_r[i] = rhs;
        g_p[i] = rhs;
        v = rhs * rhs;
    }
    float s = block_reduce(v);
    if (threadIdx.x == 0) atomicAdd(&g_rTr[0], s);
}

// Ap = M p, g_pAp[it] = p . Ap
// One row per warp, 8 warps/block, p staged in 32 KB smem, float4 streams of M.
__global__ void __launch_bounds__(256) k_matvec(const float* __restrict__ M, int n, int it) {
    if (g_rTr[it] <= CG_TOL) return;   // frozen: skip the 256 MB read entirely

    __shared__ float sp[N_MAX];        // 32 KB
    // stage p (vectorized)
    const float4* p4 = reinterpret_cast<const float4*>(g_p);
    float4* sp4w = reinterpret_cast<float4*>(sp);
    int nq = n >> 2;
    for (int j = threadIdx.x; j < nq; j += blockDim.x) sp4w[j] = p4[j];
    __syncthreads();

    int lane = threadIdx.x & 31;
    int wid  = threadIdx.x >> 5;
    int row  = blockIdx.x * 8 + wid;

    float acc = 0.0f;
    if (row < n) {
        const float4* Mrow = reinterpret_cast<const float4*>(M + (size_t)row * n);
        const float4* sp4  = reinterpret_cast<const float4*>(sp);
        #pragma unroll 4
        for (int j = lane; j < nq; j += 32) {
            float4 m = Mrow[j];
            float4 pv = sp4[j];
            acc = fmaf(m.x, pv.x, acc);
            acc = fmaf(m.y, pv.y, acc);
            acc = fmaf(m.z, pv.z, acc);
            acc = fmaf(m.w, pv.w, acc);
        }
    }
    acc = warp_reduce(acc);

    __shared__ float wpart[8];
    if (lane == 0) {
        if (row < n) {
            g_Ap[row] = acc;
            wpart[wid] = sp[row] * acc;   // p[row] * Ap[row]
        } else {
            wpart[wid] = 0.0f;
        }
    }
    __syncthreads();
    if (threadIdx.x == 0) {
        float s = wpart[0] + wpart[1] + wpart[2] + wpart[3]
                + wpart[4] + wpart[5] + wpart[6] + wpart[7];
        atomicAdd(&g_pAp[it], s);
    }
}

// alpha = rTr/pAp ; X += alpha p ; r -= alpha Ap ; g_rTr[it+1] = ||r_new||^2
__global__ void k_update_xr(int n, int it) {
    float rtr = g_rTr[it];
    bool active = rtr > CG_TOL;
    float v = 0.0f;
    if (active) {
        float alpha = rtr / g_pAp[it];
        int i = blockIdx.x * blockDim.x + threadIdx.x;
        if (i < n) {
            float p  = g_p[i];
            float ap = g_Ap[i];
            g_X[i] = fmaf(alpha, p, g_X[i]);
            float rn = fmaf(-alpha, ap, g_r[i]);
            g_r[i] = rn;
            v = rn * rn;
        }
    }
    float s = block_reduce(v);
    if (active && threadIdx.x == 0) atomicAdd(&g_rTr[it + 1], s);
}

// beta = rTr_new/rTr ; p = r + beta p
__global__ void k_update_p(int n, int it) {
    float rtr = g_rTr[it];
    if (rtr <= CG_TOL) return;
    float beta = g_rTr[it + 1] / rtr;
    int i = blockIdx.x * blockDim.x + threadIdx.x;
    if (i < n) g_p[i] = fmaf(beta, g_p[i], g_r[i]);
}

__global__ void k_writeback(float* __restrict__ out, int n) {
    int i = blockIdx.x * blockDim.x + threadIdx.x;
    if (i < n) out[i] = g_X[i];
}

extern "C" void kernel_launch(void* const* d_in, const int* in_sizes, int n_in,
                              void* d_out, int out_size) {
    // metadata order: X [n], M [n*n], RHS [n]
    const float* M   = (const float*)d_in[1];
    const float* RHS = (const float*)d_in[2];
    float* out = (float*)d_out;
    int n = in_sizes[0];

    const int T = 256;
    int vb = (n + T - 1) / T;

    k_init_scalars<<<1, 32>>>();
    k_init_vecs<<<vb, T>>>(RHS, n);

    int mv_blocks = (n + 7) / 8;
    for (int it = 0; it < CG_NITER; ++it) {
        k_matvec<<<mv_blocks, 256>>>(M, n, it);
        k_update_xr<<<vb, T>>>(n, it);
        k_update_p<<<vb, T>>>(n, it);
    }
    k_writeback<<<vb, T>>>(out, n);
}

// round 4
// speedup vs baseline: 1.0215x; 1.0215x over previous
#include <cuda_runtime.h>
#include <cuda_bf16.h>

// CG solve: X such that M X = RHS, 20 iterations, freeze once rTr <= 1e-10.
// n = 8192 (f32). Dominant cost: 20 streaming reads of the 256 MB matrix.

#define N_MAX 8192
#define CG_NITER 20
#define CG_TOL 1e-10f

// ---- persistent device state (allocation-free scratch) ----
__device__ float g_X[N_MAX];
__device__ float g_r[N_MAX];
__device__ float g_p[N_MAX];
__device__ float g_Ap[N_MAX];
__device__ float g_rTr[CG_NITER + 1];   // g_rTr[it] = ||r||^2 entering iteration it
__device__ float g_pAp[CG_NITER];

// ---- reductions ----
__device__ __forceinline__ float warp_reduce(float v) {
    #pragma unroll
    for (int o = 16; o > 0; o >>= 1) v += __shfl_xor_sync(0xffffffffu, v, o);
    return v;
}

__device__ __forceinline__ float block_reduce(float v) {
    __shared__ float sbuf[32];
    int lane = threadIdx.x & 31;
    int wid  = threadIdx.x >> 5;
    v = warp_reduce(v);
    if (lane == 0) sbuf[wid] = v;
    __syncthreads();
    int nw = (blockDim.x + 31) >> 5;
    v = (threadIdx.x < nw) ? sbuf[threadIdx.x] : 0.0f;
    if (wid == 0) v = warp_reduce(v);
    return v;
}

// ---- kernels ----

// X0 = 0, r0 = p0 = RHS, rTr[0] = sum(RHS^2); also zero scalar accumulators.
__global__ void k_init_vecs(const float* __restrict__ RHS, int n) {
    int i = blockIdx.x * blockDim.x + threadIdx.x;
    if (blockIdx.x == 0 && threadIdx.x < CG_NITER + 1) {
        g_rTr[threadIdx.x] = 0.0f;
        if (threadIdx.x < CG_NITER) g_pAp[threadIdx.x] = 0.0f;
    }
    float v = 0.0f;
    if (i < n) {
        float rhs = RHS[i];
        g_X[i] = 0.0f;
        g_r[i] = rhs;
        g_p[i] = rhs;
        v = rhs * rhs;
    }
    float s = block_reduce(v);
    if (threadIdx.x == 0) atomicAdd(&g_rTr[0], s);
}

// Ap = M p, g_pAp[it] += p . Ap  (partial per block)
// One row per warp, 8 warps/block, p staged in 32 KB smem, streaming float4 of M.
__global__ void __launch_bounds__(256) k_matvec(const float* __restrict__ M, int n, int it) {
    if (g_rTr[it] <= CG_TOL) return;   // frozen: skip the 256 MB read entirely

    __shared__ float sp[N_MAX];        // 32 KB
    const float4* p4 = reinterpret_cast<const float4*>(g_p);
    float4* sp4w = reinterpret_cast<float4*>(sp);
    int nq = n >> 2;
    for (int j = threadIdx.x; j < nq; j += blockDim.x) sp4w[j] = p4[j];
    __syncthreads();

    int lane = threadIdx.x & 31;
    int wid  = threadIdx.x >> 5;
    int row  = blockIdx.x * 8 + wid;

    float acc = 0.0f;
    if (row < n) {
        const float4* Mrow = reinterpret_cast<const float4*>(M + (size_t)row * n);
        const float4* sp4  = reinterpret_cast<const float4*>(sp);
        #pragma unroll 8
        for (int j = lane; j < nq; j += 32) {
            float4 m  = __ldcs(Mrow + j);   // streaming: no L2 retention for M
            float4 pv = sp4[j];
            acc = fmaf(m.x, pv.x, acc);
            acc = fmaf(m.y, pv.y, acc);
            acc = fmaf(m.z, pv.z, acc);
            acc = fmaf(m.w, pv.w, acc);
        }
    }
    acc = warp_reduce(acc);

    __shared__ float wpart[8];
    if (lane == 0) {
        if (row < n) {
            g_Ap[row] = acc;
            wpart[wid] = sp[row] * acc;   // p[row] * Ap[row]
        } else {
            wpart[wid] = 0.0f;
        }
    }
    __syncthreads();
    if (threadIdx.x == 0) {
        float s = wpart[0] + wpart[1] + wpart[2] + wpart[3]
                + wpart[4] + wpart[5] + wpart[6] + wpart[7];
        atomicAdd(&g_pAp[it], s);
    }
}

// Fused vector update, ONE block of 1024 threads, exactly 2 float4 per thread:
//   alpha = rTr/pAp ; X += alpha p ; r -= alpha Ap ; rTr[it+1] = ||r_new||^2
//   beta  = rTr[it+1]/rTr ; p = r_new + beta p
// r and p stay in registers across the reduction barrier.
__global__ void __launch_bounds__(1024) k_update(int n, int it) {
    float rtr = g_rTr[it];
    if (rtr <= CG_TOL) return;         // frozen: rTr[it+1] stays 0 -> stays frozen

    float4* X4  = reinterpret_cast<float4*>(g_X);
    float4* R4  = reinterpret_cast<float4*>(g_r);
    float4* P4  = reinterpret_cast<float4*>(g_p);
    const float4* AP4 = reinterpret_cast<const float4*>(g_Ap);

    float alpha = rtr / g_pAp[it];
    int q0 = threadIdx.x;
    int q1 = threadIdx.x + 1024;       // nq = 2048 for n = 8192

    float4 p0 = P4[q0], p1 = P4[q1];
    float4 a0 = AP4[q0], a1 = AP4[q1];
    float4 r0 = R4[q0], r1 = R4[q1];
    float4 x0 = X4[q0], x1 = X4[q1];

    x0.x = fmaf(alpha, p0.x, x0.x); x0.y = fmaf(alpha, p0.y, x0.y);
    x0.z = fmaf(alpha, p0.z, x0.z); x0.w = fmaf(alpha, p0.w, x0.w);
    x1.x = fmaf(alpha, p1.x, x1.x); x1.y = fmaf(alpha, p1.y, x1.y);
    x1.z = fmaf(alpha, p1.z, x1.z); x1.w = fmaf(alpha, p1.w, x1.w);
    X4[q0] = x0; X4[q1] = x1;

    r0.x = fmaf(-alpha, a0.x, r0.x); r0.y = fmaf(-alpha, a0.y, r0.y);
    r0.z = fmaf(-alpha, a0.z, r0.z); r0.w = fmaf(-alpha, a0.w, r0.w);
    r1.x = fmaf(-alpha, a1.x, r1.x); r1.y = fmaf(-alpha, a1.y, r1.y);
    r1.z = fmaf(-alpha, a1.z, r1.z); r1.w = fmaf(-alpha, a1.w, r1.w);
    R4[q0] = r0; R4[q1] = r1;

    float v = r0.x*r0.x + r0.y*r0.y + r0.z*r0.z + r0.w*r0.w
            + r1.x*r1.x + r1.y*r1.y + r1.z*r1.z + r1.w*r1.w;

    __shared__ float s_rtrn;
    float s = block_reduce(v);
    if (threadIdx.x == 0) { s_rtrn = s; g_rTr[it + 1] = s; }
    __syncthreads();

    float beta = s_rtrn / rtr;
    p0.x = fmaf(beta, p0.x, r0.x); p0.y = fmaf(beta, p0.y, r0.y);
    p0.z = fmaf(beta, p0.z, r0.z); p0.w = fmaf(beta, p0.w, r0.w);
    p1.x = fmaf(beta, p1.x, r1.x); p1.y = fmaf(beta, p1.y, r1.y);
    p1.z = fmaf(beta, p1.z, r1.z); p1.w = fmaf(beta, p1.w, r1.w);
    P4[q0] = p0; P4[q1] = p1;
}

__global__ void k_writeback(float* __restrict__ out, int n) {
    int i = blockIdx.x * blockDim.x + threadIdx.x;
    if (i < n) out[i] = g_X[i];
}

extern "C" void kernel_launch(void* const* d_in, const int* in_sizes, int n_in,
                              void* d_out, int out_size) {
    // metadata order: X [n], M [n*n], RHS [n]
    const float* M   = (const float*)d_in[1];
    const float* RHS = (const float*)d_in[2];
    float* out = (float*)d_out;
    int n = in_sizes[0];

    const int T = 256;
    int vb = (n + T - 1) / T;

    k_init_vecs<<<vb, T>>>(RHS, n);

    int mv_blocks = (n + 7) / 8;
    for (int it = 0; it < CG_NITER; ++it) {
        k_matvec<<<mv_blocks, 256>>>(M, n, it);
        k_update<<<1, 1024>>>(n, it);
    }
    k_writeback<<<vb, T>>>(out, n);
}

// round 6
// speedup vs baseline: 1.1465x; 1.1223x over previous
#include <cuda_runtime.h>
#include <cuda_bf16.h>

// CG solve: X such that M X = RHS, 20 iterations, freeze once rTr <= 1e-10.
// n = 8192 (f32). Dominant cost: 20 streaming reads of the 256 MB matrix.

#define N_MAX 8192
#define CG_NITER 20
#define CG_TOL 1e-10f

// ---- persistent device state (allocation-free scratch) ----
__device__ float g_X[N_MAX];
__device__ float g_r[N_MAX];
__device__ float g_p[N_MAX];
__device__ float g_Ap[N_MAX];
__device__ float g_rTr[CG_NITER + 1];   // g_rTr[it] = ||r||^2 entering iteration it
__device__ float g_pAp[CG_NITER];

// ---- reductions ----
__device__ __forceinline__ float warp_reduce(float v) {
    #pragma unroll
    for (int o = 16; o > 0; o >>= 1) v += __shfl_xor_sync(0xffffffffu, v, o);
    return v;
}

__device__ __forceinline__ float block_reduce(float v) {
    __shared__ float sbuf[32];
    int lane = threadIdx.x & 31;
    int wid  = threadIdx.x >> 5;
    v = warp_reduce(v);
    if (lane == 0) sbuf[wid] = v;
    __syncthreads();
    int nw = (blockDim.x + 31) >> 5;
    v = (threadIdx.x < nw) ? sbuf[threadIdx.x] : 0.0f;
    if (wid == 0) v = warp_reduce(v);
    return v;
}

// ---- kernels ----

// X0 = 0, r0 = p0 = RHS, rTr[0] = sum(RHS^2); also zero scalar accumulators.
__global__ void k_init_vecs(const float* __restrict__ RHS, int n) {
    int i = blockIdx.x * blockDim.x + threadIdx.x;
    if (blockIdx.x == 0 && threadIdx.x < CG_NITER + 1) {
        g_rTr[threadIdx.x] = 0.0f;
        if (threadIdx.x < CG_NITER) g_pAp[threadIdx.x] = 0.0f;
    }
    float v = 0.0f;
    if (i < n) {
        float rhs = RHS[i];
        g_X[i] = 0.0f;
        g_r[i] = rhs;
        g_p[i] = rhs;
        v = rhs * rhs;
    }
    float s = block_reduce(v);
    if (threadIdx.x == 0) atomicAdd(&g_rTr[0], s);
}

// Ap = M p, g_pAp[it] += p . Ap  (partial per block)
// 512 threads = 16 warps, one row per warp. grid = 8192/16 = 512 blocks
// -> 4 blocks/SM (64 warps, 128 KB smem): EXACTLY one wave, no tail.
// p staged in 32 KB smem; M streamed with __ldcs; 4 accumulators per thread.
__global__ void __launch_bounds__(512) k_matvec(const float* __restrict__ M, int n, int it) {
    if (g_rTr[it] <= CG_TOL) return;   // frozen: skip the 256 MB read entirely

    __shared__ float sp[N_MAX];        // 32 KB
    const float4* p4 = reinterpret_cast<const float4*>(g_p);
    float4* sp4w = reinterpret_cast<float4*>(sp);
    int nq = n >> 2;                   // 2048
    for (int j = threadIdx.x; j < nq; j += blockDim.x) sp4w[j] = p4[j];
    __syncthreads();

    int lane = threadIdx.x & 31;
    int wid  = threadIdx.x >> 5;       // 0..15
    int row  = blockIdx.x * 16 + wid;

    float a0 = 0.0f, a1 = 0.0f, a2 = 0.0f, a3 = 0.0f;
    {
        const float4* Mrow = reinterpret_cast<const float4*>(M + (size_t)row * n);
        const float4* sp4  = reinterpret_cast<const float4*>(sp);
        #pragma unroll 8
        for (int j = lane; j < nq; j += 32) {
            float4 m  = __ldcs(Mrow + j);   // streaming: no L2 retention for M
            float4 pv = sp4[j];
            a0 = fmaf(m.x, pv.x, a0);
            a1 = fmaf(m.y, pv.y, a1);
            a2 = fmaf(m.z, pv.z, a2);
            a3 = fmaf(m.w, pv.w, a3);
        }
    }
    float acc = (a0 + a1) + (a2 + a3);
    acc = warp_reduce(acc);

    __shared__ float wpart[16];
    if (lane == 0) {
        g_Ap[row] = acc;
        wpart[wid] = sp[row] * acc;        // p[row] * Ap[row]
    }
    __syncthreads();
    if (threadIdx.x == 0) {
        float s = 0.0f;
        #pragma unroll
        for (int w = 0; w < 16; ++w) s += wpart[w];
        atomicAdd(&g_pAp[it], s);
    }
}

// Fused vector update, ONE block of 1024 threads, exactly 2 float4 per thread:
//   alpha = rTr/pAp ; X += alpha p ; r -= alpha Ap ; rTr[it+1] = ||r_new||^2
//   beta  = rTr[it+1]/rTr ; p = r_new + beta p
// r and p stay in registers across the reduction barrier.
__global__ void __launch_bounds__(1024) k_update(int n, int it) {
    float rtr = g_rTr[it];
    if (rtr <= CG_TOL) return;         // frozen: rTr[it+1] stays 0 -> stays frozen

    float4* X4  = reinterpret_cast<float4*>(g_X);
    float4* R4  = reinterpret_cast<float4*>(g_r);
    float4* P4  = reinterpret_cast<float4*>(g_p);
    const float4* AP4 = reinterpret_cast<const float4*>(g_Ap);

    float alpha = rtr / g_pAp[it];
    int q0 = threadIdx.x;
    int q1 = threadIdx.x + 1024;       // nq = 2048 for n = 8192

    float4 p0 = P4[q0], p1 = P4[q1];
    float4 a0 = AP4[q0], a1 = AP4[q1];
    float4 r0 = R4[q0], r1 = R4[q1];
    float4 x0 = X4[q0], x1 = X4[q1];

    x0.x = fmaf(alpha, p0.x, x0.x); x0.y = fmaf(alpha, p0.y, x0.y);
    x0.z = fmaf(alpha, p0.z, x0.z); x0.w = fmaf(alpha, p0.w, x0.w);
    x1.x = fmaf(alpha, p1.x, x1.x); x1.y = fmaf(alpha, p1.y, x1.y);
    x1.z = fmaf(alpha, p1.z, x1.z); x1.w = fmaf(alpha, p1.w, x1.w);
    X4[q0] = x0; X4[q1] = x1;

    r0.x = fmaf(-alpha, a0.x, r0.x); r0.y = fmaf(-alpha, a0.y, r0.y);
    r0.z = fmaf(-alpha, a0.z, r0.z); r0.w = fmaf(-alpha, a0.w, r0.w);
    r1.x = fmaf(-alpha, a1.x, r1.x); r1.y = fmaf(-alpha, a1.y, r1.y);
    r1.z = fmaf(-alpha, a1.z, r1.z); r1.w = fmaf(-alpha, a1.w, r1.w);
    R4[q0] = r0; R4[q1] = r1;

    float v = r0.x*r0.x + r0.y*r0.y + r0.z*r0.z + r0.w*r0.w
            + r1.x*r1.x + r1.y*r1.y + r1.z*r1.z + r1.w*r1.w;

    __shared__ float s_rtrn;
    float s = block_reduce(v);
    if (threadIdx.x == 0) { s_rtrn = s; g_rTr[it + 1] = s; }
    __syncthreads();

    float beta = s_rtrn / rtr;
    p0.x = fmaf(beta, p0.x, r0.x); p0.y = fmaf(beta, p0.y, r0.y);
    p0.z = fmaf(beta, p0.z, r0.z); p0.w = fmaf(beta, p0.w, r0.w);
    p1.x = fmaf(beta, p1.x, r1.x); p1.y = fmaf(beta, p1.y, r1.y);
    p1.z = fmaf(beta, p1.z, r1.z); p1.w = fmaf(beta, p1.w, r1.w);
    P4[q0] = p0; P4[q1] = p1;
}

__global__ void k_writeback(float* __restrict__ out, int n) {
    int i = blockIdx.x * blockDim.x + threadIdx.x;
    if (i < n) out[i] = g_X[i];
}

extern "C" void kernel_launch(void* const* d_in, const int* in_sizes, int n_in,
                              void* d_out, int out_size) {
    // metadata order: X [n], M [n*n], RHS [n]
    const float* M   = (const float*)d_in[1];
    const float* RHS = (const float*)d_in[2];
    float* out = (float*)d_out;
    int n = in_sizes[0];

    const int T = 256;
    int vb = (n + T - 1) / T;

    k_init_vecs<<<vb, T>>>(RHS, n);

    int mv_blocks = n / 16;            // 512 blocks, one wave
    for (int it = 0; it < CG_NITER; ++it) {
        k_matvec<<<mv_blocks, 512>>>(M, n, it);
        k_update<<<1, 1024>>>(n, it);
    }
    k_writeback<<<vb, T>>>(out, n);
}